// round 11
// baseline (speedup 1.0000x reference)
#include <cuda_runtime.h>
#include <cuda_fp16.h>
#include <math.h>
#include <stdint.h>

// MoE Router: 1-term fp16 mma.sync GEMM + exact fp32 refinement of marginal tokens.
// logits ~= fp16(x) @ fp16(w)^T + b  (norm-rel err ~4e-4, within 1e-3 tolerance).
// Tokens whose top-3 margins are < THETA get exact fp32 recompute in pass 2,
// so indices/weights/mask are effectively exact.
// T=16384, D=4096, E=64, top-2.
// Output (float32, concatenated):
//   [0, T*E)     logits [T,E]
//   [+T*2)       weights [T,2]
//   [+T*2)       indices [T,2] (as float)
//   [+E*2*T)     expert_mask [E,2,T]

#define Dk 4096
#define Ek 64
#define TOPK 2
#define BM 128        // tokens per CTA
#define KC 64         // k per chunk (64 fp16 = 128B row)
#define NCHUNK (Dk / KC)
#define THETA 4e-3f

// device scratch
__device__ __half g_w1[Ek * Dk];    // fp16 gate weights, [E][Dk] k-major
__device__ int    g_flagcnt;
__device__ int    g_flags[16384];

// ---------------- smem layout (dynamic) ----------------
#define SM_BIAS 64
#define X1B(b) (1024 + (b) * 24576)
#define W1B(b) (X1B(b) + 16384)
#define SM_LG 1024                // 32KB logits scratch, reuses buffers (dead after loop)
#define SMEM_TOTAL (1024 + 2 * 24576)

// ---------------- helpers ----------------
__device__ __forceinline__ uint32_t smem_u32(const void* p) {
    uint32_t a;
    asm("{ .reg .u64 t; cvta.to.shared.u64 t, %1; cvt.u32.u64 %0, t; }" : "=r"(a) : "l"(p));
    return a;
}
// pack two floats to f16x2: dest.hi = hi, dest.lo = lo
__device__ __forceinline__ uint32_t pack2h(float hi, float lo) {
    uint32_t r;
    asm("cvt.rn.f16x2.f32 %0, %1, %2;" : "=r"(r) : "f"(hi), "f"(lo));
    return r;
}
// float4 -> 4 fp16 packed (memory order x,y / z,w)
__device__ __forceinline__ uint2 cvt4h(float4 v) {
    return make_uint2(pack2h(v.y, v.x), pack2h(v.w, v.z));
}
__device__ __forceinline__ void ldm_x4(uint32_t* r, uint32_t addr) {
    asm volatile("ldmatrix.sync.aligned.m8n8.x4.shared.b16 {%0,%1,%2,%3}, [%4];"
        : "=r"(r[0]), "=r"(r[1]), "=r"(r[2]), "=r"(r[3]) : "r"(addr));
}
__device__ __forceinline__ void mma_f16(float* c, const uint32_t* a, uint32_t b0, uint32_t b1) {
    asm volatile("mma.sync.aligned.m16n8k16.row.col.f32.f16.f16.f32 "
        "{%0,%1,%2,%3}, {%4,%5,%6,%7}, {%8,%9}, {%0,%1,%2,%3};"
        : "+f"(c[0]), "+f"(c[1]), "+f"(c[2]), "+f"(c[3])
        : "r"(a[0]), "r"(a[1]), "r"(a[2]), "r"(a[3]), "r"(b0), "r"(b1));
}

// ---------------- aux kernel: convert w to fp16 + reset flag counter ----------------
__global__ void w_prep_kernel(const float4* __restrict__ gw4) {
    int i = blockIdx.x * blockDim.x + threadIdx.x;   // 65536 float4s
    if (i == 0) g_flagcnt = 0;
    ((uint2*)g_w1)[i] = cvt4h(gw4[i]);
}

// ---------------- pass 1: fp16 GEMM + epilogue + flagging ----------------
__global__ __launch_bounds__(256, 1)
void moe_router_mma(const float* __restrict__ x,
                    const float* __restrict__ gb,
                    float* __restrict__ out, int T)
{
    extern __shared__ char smem[];
    const uint32_t sb = smem_u32(smem);
    const int tid = threadIdx.x;
    const int lid = tid & 31;
    const int wid = tid >> 5;
    const int t0 = blockIdx.x * BM;

    const size_t offW = (size_t)T * Ek;
    const size_t offI = offW + (size_t)T * TOPK;
    const size_t offM = offI + (size_t)T * TOPK;

    if (tid < 16) ((float4*)(smem + SM_BIAS))[tid] = ((const float4*)gb)[tid];

    // zero this CTA's slice of expert_mask: all 128 (e,k) rows, cols [t0, t0+128)
    {
        float4 z4 = make_float4(0.f, 0.f, 0.f, 0.f);
        float* mbase = out + offM + t0;
#pragma unroll
        for (int i = tid; i < 128 * 32; i += 256) {
            int row = i >> 5, col = i & 31;
            ((float4*)(mbase + (size_t)row * T))[col] = z4;
        }
    }

    // ---- loader geometry ----
    const int xr = tid >> 4;   // x row group 0..15 (rows xr + 16*it)
    const int xj = tid & 15;   // 16B fp32-col group / 8B fp16 segment
    uint32_t x_sts[8];
#pragma unroll
    for (int it = 0; it < 8; ++it) {
        int row = xr + 16 * it;
        x_sts[it] = (uint32_t)(row * 128 + ((xj * 8) ^ ((row & 7) << 4)));
    }
    int wrow[2], wseg[2];
    uint32_t w_sts[2];
#pragma unroll
    for (int it = 0; it < 2; ++it) {
        int idx = it * 256 + tid;
        wrow[it] = idx >> 3; wseg[it] = idx & 7;
        w_sts[it] = (uint32_t)(wrow[it] * 128 + ((wseg[it] * 16) ^ ((wrow[it] & 7) << 4)));
    }

    // ---- mma geometry: warp tile 32(m) x 32(n) ----
    const int wm = wid & 3;
    const int wn = wid >> 2;
    const int lrow = lid & 15;
    const int lhi = (lid >> 4) << 4;
    const int rsw = (lrow & 7) << 4;
    int arow[2], brow[2];
#pragma unroll
    for (int mi = 0; mi < 2; ++mi) arow[mi] = (32 * wm + 16 * mi + lrow) * 128;
#pragma unroll
    for (int g = 0; g < 2; ++g)  brow[g]  = (32 * wn + 16 * g + lrow) * 128;

    float acc[2][4][4];
#pragma unroll
    for (int mi = 0; mi < 2; ++mi)
#pragma unroll
        for (int nj = 0; nj < 4; ++nj)
#pragma unroll
            for (int q = 0; q < 4; ++q) acc[mi][nj][q] = 0.f;

    // ---- prologue: stage chunk 0 ----
    {
        const float* xp = x + (size_t)(t0 + xr) * Dk + 4 * xj;
#pragma unroll
        for (int it = 0; it < 8; ++it)
            *(uint2*)(smem + X1B(0) + x_sts[it]) = cvt4h(*(const float4*)(xp + (size_t)(16 * it) * Dk));
#pragma unroll
        for (int it = 0; it < 2; ++it) {
            const size_t eoff = (size_t)wrow[it] * Dk + wseg[it] * 8;
            *(uint4*)(smem + W1B(0) + w_sts[it]) = *(const uint4*)((const char*)g_w1 + eoff * 2);
        }
    }
    __syncthreads();

    // ---- main loop ----
    for (int c = 0; c < NCHUNK; ++c) {
        const int b = c & 1;
        const bool more = (c + 1 < NCHUNK);

        // 1) LDG next chunk
        float4 xv[8];
        uint4 w1v[2];
        if (more) {
            const int d1 = (c + 1) * KC;
            const float* xp = x + (size_t)(t0 + xr) * Dk + d1 + 4 * xj;
#pragma unroll
            for (int it = 0; it < 8; ++it)
                xv[it] = *(const float4*)(xp + (size_t)(16 * it) * Dk);
#pragma unroll
            for (int it = 0; it < 2; ++it) {
                const size_t eoff = (size_t)wrow[it] * Dk + d1 + wseg[it] * 8;
                w1v[it] = *(const uint4*)((const char*)g_w1 + eoff * 2);
            }
        }

        // 2) compute current chunk
        {
            const uint32_t x1_b = sb + X1B(b), w1_b = sb + W1B(b);
#pragma unroll
            for (int ks = 0; ks < 4; ++ks) {
                const uint32_t kb = (uint32_t)((ks * 32 + lhi) ^ rsw);
                uint32_t a1[2][4], b1[2][4];
#pragma unroll
                for (int mi = 0; mi < 2; ++mi) ldm_x4(a1[mi], x1_b + arow[mi] + kb);
#pragma unroll
                for (int g = 0; g < 2; ++g)   ldm_x4(b1[g], w1_b + brow[g] + kb);
#pragma unroll
                for (int mi = 0; mi < 2; ++mi)
#pragma unroll
                    for (int nj = 0; nj < 4; ++nj) {
                        const int g = nj >> 1, hf = nj & 1;
                        mma_f16(acc[mi][nj], a1[mi], b1[g][hf], b1[g][hf + 2]);
                    }
            }
        }

        // 3) convert + store next chunk
        if (more) {
            const int nb = 1 - b;
#pragma unroll
            for (int it = 0; it < 8; ++it)
                *(uint2*)(smem + X1B(nb) + x_sts[it]) = cvt4h(xv[it]);
#pragma unroll
            for (int it = 0; it < 2; ++it)
                *(uint4*)(smem + W1B(nb) + w_sts[it]) = w1v[it];
        }
        __syncthreads();
    }

    // ---- epilogue: acc -> smem logits ----
    float* lg = (float*)(smem + SM_LG);
    {
        const int crow = 32 * wm + (lid >> 2);
        const int ccol = 32 * wn + (lid & 3) * 2;
#pragma unroll
        for (int mi = 0; mi < 2; ++mi)
#pragma unroll
            for (int nj = 0; nj < 4; ++nj) {
                const int r = crow + 16 * mi, cc = ccol + 8 * nj;
                *(float2*)&lg[r * Ek + cc]       = make_float2(acc[mi][nj][0], acc[mi][nj][1]);
                *(float2*)&lg[(r + 8) * Ek + cc] = make_float2(acc[mi][nj][2], acc[mi][nj][3]);
            }
    }
    __syncthreads();

    // add bias, write logits to gmem + smem
    const float* bs = (const float*)(smem + SM_BIAS);
    {
        const int tl = tid >> 1, eh = (tid & 1) * 32;
        float* lr = lg + tl * Ek + eh;
        float4* orow = (float4*)(out + (size_t)(t0 + tl) * Ek + eh);
#pragma unroll
        for (int q = 0; q < 8; ++q) {
            float4 v = *(float4*)(lr + 4 * q);
            v.x += bs[eh + 4 * q + 0];
            v.y += bs[eh + 4 * q + 1];
            v.z += bs[eh + 4 * q + 2];
            v.w += bs[eh + 4 * q + 3];
            orow[q] = v;
            *(float4*)(lr + 4 * q) = v;
        }
    }
    __syncthreads();

    // per-token: top-3, margin test -> flag or write outputs
    if (tid < BM) {
        const int t = t0 + tid;
        const float* lr = lg + tid * Ek;
        float m1 = -INFINITY, m2 = -INFINITY, m3 = -INFINITY;
        int i1 = 0, i2 = 0;
#pragma unroll
        for (int e = 0; e < Ek; ++e) {
            float z = lr[e];
            if (z > m1)      { m3 = m2; m2 = m1; i2 = i1; m1 = z; i1 = e; }
            else if (z > m2) { m3 = m2; m2 = z; i2 = e; }
            else if (z > m3) { m3 = z; }
        }
        if ((m1 - m2 < THETA) || (m2 - m3 < THETA)) {
            int slot = atomicAdd(&g_flagcnt, 1);
            g_flags[slot] = t;
        } else {
            float ed = expf(m2 - m1);
            float w1 = 1.0f / (1.0f + ed);
            float w2 = ed * w1;
            out[offW + (size_t)t * TOPK + 0] = w1;
            out[offW + (size_t)t * TOPK + 1] = w2;
            out[offI + (size_t)t * TOPK + 0] = (float)i1;
            out[offI + (size_t)t * TOPK + 1] = (float)i2;
            out[offM + ((size_t)i1 * TOPK + 0) * (size_t)T + t] = 1.0f;
            out[offM + ((size_t)i2 * TOPK + 1) * (size_t)T + t] = 1.0f;
        }
    }
}

// ---------------- pass 2: exact fp32 refinement of flagged tokens ----------------
__global__ __launch_bounds__(256)
void refine_kernel(const float* __restrict__ x,
                   const float* __restrict__ gw,
                   const float* __restrict__ gb,
                   float* __restrict__ out, int T)
{
    __shared__ float xs[Dk];
    __shared__ float lg[Ek];
    const int tid = threadIdx.x;
    const int wid = tid >> 5, lid = tid & 31;
    const int nflag = g_flagcnt;

    const size_t offW = (size_t)T * Ek;
    const size_t offI = offW + (size_t)T * TOPK;
    const size_t offM = offI + (size_t)T * TOPK;

    for (int fi = blockIdx.x; fi < nflag; fi += gridDim.x) {
        const int t = g_flags[fi];
        __syncthreads();   // protect smem reuse across iterations
        for (int i = tid; i < Dk / 4; i += 256)
            ((float4*)xs)[i] = ((const float4*)(x + (size_t)t * Dk))[i];
        __syncthreads();

        // 8 warps x 8 experts each, exact fp32 dot
#pragma unroll 1
        for (int e8 = 0; e8 < 8; ++e8) {
            const int e = wid * 8 + e8;
            const float4* wr = (const float4*)(gw + (size_t)e * Dk);
            float a = 0.f;
            for (int i = lid; i < Dk / 4; i += 32) {
                float4 wv = wr[i];
                float4 xv = ((const float4*)xs)[i];
                a = fmaf(xv.x, wv.x, a); a = fmaf(xv.y, wv.y, a);
                a = fmaf(xv.z, wv.z, a); a = fmaf(xv.w, wv.w, a);
            }
#pragma unroll
            for (int o = 16; o > 0; o >>= 1) a += __shfl_xor_sync(0xFFFFFFFFu, a, o);
            if (lid == 0) lg[e] = a + gb[e];
        }
        __syncthreads();

        if (tid < 16)   // overwrite logits row with exact values
            ((float4*)(out + (size_t)t * Ek))[tid] = ((const float4*)lg)[tid];

        if (tid == 0) {
            float m1 = -INFINITY, m2 = -INFINITY;
            int i1 = 0, i2 = 0;
#pragma unroll
            for (int e = 0; e < Ek; ++e) {
                float z = lg[e];
                if (z > m1)      { m2 = m1; i2 = i1; m1 = z; i1 = e; }
                else if (z > m2) { m2 = z; i2 = e; }
            }
            float ed = expf(m2 - m1);
            float w1 = 1.0f / (1.0f + ed);
            float w2 = ed * w1;
            out[offW + (size_t)t * TOPK + 0] = w1;
            out[offW + (size_t)t * TOPK + 1] = w2;
            out[offI + (size_t)t * TOPK + 0] = (float)i1;
            out[offI + (size_t)t * TOPK + 1] = (float)i2;
            out[offM + ((size_t)i1 * TOPK + 0) * (size_t)T + t] = 1.0f;
            out[offM + ((size_t)i2 * TOPK + 1) * (size_t)T + t] = 1.0f;
        }
    }
}

extern "C" void kernel_launch(void* const* d_in, const int* in_sizes, int n_in,
                              void* d_out, int out_size)
{
    const float* x  = (const float*)d_in[0];
    const float* gw = (const float*)d_in[1];
    const float* gb = (const float*)d_in[2];
    float* out = (float*)d_out;
    const int T = in_sizes[0] / Dk;

    cudaFuncSetAttribute(moe_router_mma, cudaFuncAttributeMaxDynamicSharedMemorySize, SMEM_TOTAL);

    w_prep_kernel<<<256, 256>>>((const float4*)gw);           // fp16 w + flag reset
    moe_router_mma<<<T / BM, 256, SMEM_TOTAL>>>(x, gb, out, T);
    refine_kernel<<<64, 256>>>(x, gw, gb, out, T);
}

// round 12
// speedup vs baseline: 2.7090x; 2.7090x over previous
#include <cuda_runtime.h>
#include <cuda_fp16.h>
#include <math.h>
#include <stdint.h>

// MoE Router: 1-term fp16 mma.sync GEMM + candidate-only exact fp32 refinement.
// Pass 1: logits ~= fp16(x) @ fp16(w)^T + b (per-logit err ~3e-4 < 1e-3 tol).
//         Tokens with top-3 margins < THETA are flagged, others finalized.
// Pass 2: one warp per flagged token; exact fp32 recompute of only the experts
//         within CAND_WIN of approx-m2 -> exact top-2 indices/weights/mask.
// T=16384, D=4096, E=64, top-2.
// Output (float32, concatenated): logits [T,E] | weights [T,2] | indices [T,2] | mask [E,2,T]

#define Dk 4096
#define Ek 64
#define TOPK 2
#define BM 128
#define KC 64
#define NCHUNK (Dk / KC)
#define THETA    2.5e-3f
#define CAND_WIN 5.0e-3f

__device__ __half g_w1[Ek * Dk];    // fp16 gate weights, [E][Dk] k-major
__device__ int    g_flagcnt;
__device__ int    g_flags[16384];

// ---------------- smem layout ----------------
#define SM_BIAS 64
#define X1B(b) (1024 + (b) * 24576)
#define W1B(b) (X1B(b) + 16384)
#define SM_LG 1024
#define SMEM_TOTAL (1024 + 2 * 24576)

// ---------------- helpers ----------------
__device__ __forceinline__ uint32_t smem_u32(const void* p) {
    uint32_t a;
    asm("{ .reg .u64 t; cvta.to.shared.u64 t, %1; cvt.u32.u64 %0, t; }" : "=r"(a) : "l"(p));
    return a;
}
__device__ __forceinline__ uint32_t pack2h(float hi, float lo) {
    uint32_t r;
    asm("cvt.rn.f16x2.f32 %0, %1, %2;" : "=r"(r) : "f"(hi), "f"(lo));
    return r;
}
__device__ __forceinline__ uint2 cvt4h(float4 v) {
    return make_uint2(pack2h(v.y, v.x), pack2h(v.w, v.z));
}
__device__ __forceinline__ void ldm_x4(uint32_t* r, uint32_t addr) {
    asm volatile("ldmatrix.sync.aligned.m8n8.x4.shared.b16 {%0,%1,%2,%3}, [%4];"
        : "=r"(r[0]), "=r"(r[1]), "=r"(r[2]), "=r"(r[3]) : "r"(addr));
}
__device__ __forceinline__ void mma_f16(float* c, const uint32_t* a, uint32_t b0, uint32_t b1) {
    asm volatile("mma.sync.aligned.m16n8k16.row.col.f32.f16.f16.f32 "
        "{%0,%1,%2,%3}, {%4,%5,%6,%7}, {%8,%9}, {%0,%1,%2,%3};"
        : "+f"(c[0]), "+f"(c[1]), "+f"(c[2]), "+f"(c[3])
        : "r"(a[0]), "r"(a[1]), "r"(a[2]), "r"(a[3]), "r"(b0), "r"(b1));
}

// ---------------- aux: convert w to fp16 + reset flag counter ----------------
__global__ void w_prep_kernel(const float4* __restrict__ gw4) {
    int i = blockIdx.x * blockDim.x + threadIdx.x;
    if (i == 0) g_flagcnt = 0;
    ((uint2*)g_w1)[i] = cvt4h(gw4[i]);
}

// ---------------- pass 1 ----------------
__global__ __launch_bounds__(256, 1)
void moe_router_mma(const float* __restrict__ x,
                    const float* __restrict__ gb,
                    float* __restrict__ out, int T)
{
    extern __shared__ char smem[];
    const uint32_t sb = smem_u32(smem);
    const int tid = threadIdx.x;
    const int lid = tid & 31;
    const int wid = tid >> 5;
    const int t0 = blockIdx.x * BM;

    const size_t offW = (size_t)T * Ek;
    const size_t offI = offW + (size_t)T * TOPK;
    const size_t offM = offI + (size_t)T * TOPK;

    if (tid < 16) ((float4*)(smem + SM_BIAS))[tid] = ((const float4*)gb)[tid];

    // zero this CTA's slice of expert_mask: 128 (e,k) rows, cols [t0, t0+128)
    {
        float4 z4 = make_float4(0.f, 0.f, 0.f, 0.f);
        float* mbase = out + offM + t0;
#pragma unroll
        for (int i = tid; i < 128 * 32; i += 256) {
            int row = i >> 5, col = i & 31;
            ((float4*)(mbase + (size_t)row * T))[col] = z4;
        }
    }

    // loader geometry
    const int xr = tid >> 4;
    const int xj = tid & 15;
    uint32_t x_sts[8];
#pragma unroll
    for (int it = 0; it < 8; ++it) {
        int row = xr + 16 * it;
        x_sts[it] = (uint32_t)(row * 128 + ((xj * 8) ^ ((row & 7) << 4)));
    }
    int wrow[2], wseg[2];
    uint32_t w_sts[2];
#pragma unroll
    for (int it = 0; it < 2; ++it) {
        int idx = it * 256 + tid;
        wrow[it] = idx >> 3; wseg[it] = idx & 7;
        w_sts[it] = (uint32_t)(wrow[it] * 128 + ((wseg[it] * 16) ^ ((wrow[it] & 7) << 4)));
    }

    // mma geometry: warp tile 32x32
    const int wm = wid & 3;
    const int wn = wid >> 2;
    const int lrow = lid & 15;
    const int lhi = (lid >> 4) << 4;
    const int rsw = (lrow & 7) << 4;
    int arow[2], brow[2];
#pragma unroll
    for (int mi = 0; mi < 2; ++mi) arow[mi] = (32 * wm + 16 * mi + lrow) * 128;
#pragma unroll
    for (int g = 0; g < 2; ++g)  brow[g]  = (32 * wn + 16 * g + lrow) * 128;

    float acc[2][4][4];
#pragma unroll
    for (int mi = 0; mi < 2; ++mi)
#pragma unroll
        for (int nj = 0; nj < 4; ++nj)
#pragma unroll
            for (int q = 0; q < 4; ++q) acc[mi][nj][q] = 0.f;

    // prologue
    {
        const float* xp = x + (size_t)(t0 + xr) * Dk + 4 * xj;
#pragma unroll
        for (int it = 0; it < 8; ++it)
            *(uint2*)(smem + X1B(0) + x_sts[it]) = cvt4h(*(const float4*)(xp + (size_t)(16 * it) * Dk));
#pragma unroll
        for (int it = 0; it < 2; ++it) {
            const size_t eoff = (size_t)wrow[it] * Dk + wseg[it] * 8;
            *(uint4*)(smem + W1B(0) + w_sts[it]) = *(const uint4*)((const char*)g_w1 + eoff * 2);
        }
    }
    __syncthreads();

    // main loop
    for (int c = 0; c < NCHUNK; ++c) {
        const int b = c & 1;
        const bool more = (c + 1 < NCHUNK);

        float4 xv[8];
        uint4 w1v[2];
        if (more) {
            const int d1 = (c + 1) * KC;
            const float* xp = x + (size_t)(t0 + xr) * Dk + d1 + 4 * xj;
#pragma unroll
            for (int it = 0; it < 8; ++it)
                xv[it] = *(const float4*)(xp + (size_t)(16 * it) * Dk);
#pragma unroll
            for (int it = 0; it < 2; ++it) {
                const size_t eoff = (size_t)wrow[it] * Dk + d1 + wseg[it] * 8;
                w1v[it] = *(const uint4*)((const char*)g_w1 + eoff * 2);
            }
        }

        {
            const uint32_t x1_b = sb + X1B(b), w1_b = sb + W1B(b);
#pragma unroll
            for (int ks = 0; ks < 4; ++ks) {
                const uint32_t kb = (uint32_t)((ks * 32 + lhi) ^ rsw);
                uint32_t a1[2][4], b1[2][4];
#pragma unroll
                for (int mi = 0; mi < 2; ++mi) ldm_x4(a1[mi], x1_b + arow[mi] + kb);
#pragma unroll
                for (int g = 0; g < 2; ++g)   ldm_x4(b1[g], w1_b + brow[g] + kb);
#pragma unroll
                for (int mi = 0; mi < 2; ++mi)
#pragma unroll
                    for (int nj = 0; nj < 4; ++nj) {
                        const int g = nj >> 1, hf = nj & 1;
                        mma_f16(acc[mi][nj], a1[mi], b1[g][hf], b1[g][hf + 2]);
                    }
            }
        }

        if (more) {
            const int nb = 1 - b;
#pragma unroll
            for (int it = 0; it < 8; ++it)
                *(uint2*)(smem + X1B(nb) + x_sts[it]) = cvt4h(xv[it]);
#pragma unroll
            for (int it = 0; it < 2; ++it)
                *(uint4*)(smem + W1B(nb) + w_sts[it]) = w1v[it];
        }
        __syncthreads();
    }

    // epilogue: acc -> smem logits
    float* lg = (float*)(smem + SM_LG);
    {
        const int crow = 32 * wm + (lid >> 2);
        const int ccol = 32 * wn + (lid & 3) * 2;
#pragma unroll
        for (int mi = 0; mi < 2; ++mi)
#pragma unroll
            for (int nj = 0; nj < 4; ++nj) {
                const int r = crow + 16 * mi, cc = ccol + 8 * nj;
                *(float2*)&lg[r * Ek + cc]       = make_float2(acc[mi][nj][0], acc[mi][nj][1]);
                *(float2*)&lg[(r + 8) * Ek + cc] = make_float2(acc[mi][nj][2], acc[mi][nj][3]);
            }
    }
    __syncthreads();

    const float* bs = (const float*)(smem + SM_BIAS);
    {
        const int tl = tid >> 1, eh = (tid & 1) * 32;
        float* lr = lg + tl * Ek + eh;
        float4* orow = (float4*)(out + (size_t)(t0 + tl) * Ek + eh);
#pragma unroll
        for (int q = 0; q < 8; ++q) {
            float4 v = *(float4*)(lr + 4 * q);
            v.x += bs[eh + 4 * q + 0];
            v.y += bs[eh + 4 * q + 1];
            v.z += bs[eh + 4 * q + 2];
            v.w += bs[eh + 4 * q + 3];
            orow[q] = v;
            *(float4*)(lr + 4 * q) = v;
        }
    }
    __syncthreads();

    // per-token: top-3 margin test -> finalize or flag
    if (tid < BM) {
        const int t = t0 + tid;
        const float* lr = lg + tid * Ek;
        float m1 = -INFINITY, m2 = -INFINITY, m3 = -INFINITY;
        int i1 = 0, i2 = 0;
#pragma unroll
        for (int e = 0; e < Ek; ++e) {
            float z = lr[e];
            if (z > m1)      { m3 = m2; m2 = m1; i2 = i1; m1 = z; i1 = e; }
            else if (z > m2) { m3 = m2; m2 = z; i2 = e; }
            else if (z > m3) { m3 = z; }
        }
        if ((m1 - m2 < THETA) || (m2 - m3 < THETA)) {
            int slot = atomicAdd(&g_flagcnt, 1);
            g_flags[slot] = t;
        } else {
            float ed = expf(m2 - m1);
            float w1 = 1.0f / (1.0f + ed);
            float w2 = ed * w1;
            out[offW + (size_t)t * TOPK + 0] = w1;
            out[offW + (size_t)t * TOPK + 1] = w2;
            out[offI + (size_t)t * TOPK + 0] = (float)i1;
            out[offI + (size_t)t * TOPK + 1] = (float)i2;
            out[offM + ((size_t)i1 * TOPK + 0) * (size_t)T + t] = 1.0f;
            out[offM + ((size_t)i2 * TOPK + 1) * (size_t)T + t] = 1.0f;
        }
    }
}

// ---------------- pass 2: candidate-only exact refinement, warp per token ----------------
__device__ __forceinline__ float warp_dot4k(const float4* __restrict__ xr,
                                            const float4* __restrict__ wr, int lid) {
    float a = 0.f;
#pragma unroll 8
    for (int i = lid; i < Dk / 4; i += 32) {
        float4 xv = xr[i], wv = wr[i];
        a = fmaf(xv.x, wv.x, a); a = fmaf(xv.y, wv.y, a);
        a = fmaf(xv.z, wv.z, a); a = fmaf(xv.w, wv.w, a);
    }
#pragma unroll
    for (int o = 16; o > 0; o >>= 1) a += __shfl_xor_sync(0xFFFFFFFFu, a, o);
    return a;
}

__global__ __launch_bounds__(256)
void refine_kernel(const float* __restrict__ x,
                   const float* __restrict__ gw,
                   const float* __restrict__ gb,
                   float* __restrict__ out, int T)
{
    const int lid = threadIdx.x & 31;
    const int gwarp = (blockIdx.x * blockDim.x + threadIdx.x) >> 5;
    const int nwarps = (gridDim.x * blockDim.x) >> 5;
    const int nflag = g_flagcnt;

    const size_t offW = (size_t)T * Ek;
    const size_t offI = offW + (size_t)T * TOPK;
    const size_t offM = offI + (size_t)T * TOPK;

    for (int fi = gwarp; fi < nflag; fi += nwarps) {
        const int t = g_flags[fi];
        const float* lrow = out + (size_t)t * Ek;
        float l0 = lrow[lid];         // experts lid, lid+32
        float l1 = lrow[lid + 32];

        // approx top-2 value (values only) across warp to set candidate window
        float a1 = fmaxf(l0, l1), a2 = fminf(l0, l1);
#pragma unroll
        for (int o = 16; o > 0; o >>= 1) {
            float b1v = __shfl_xor_sync(0xFFFFFFFFu, a1, o);
            float b2v = __shfl_xor_sync(0xFFFFFFFFu, a2, o);
            // merge {a1,a2} with {b1v,b2v}
            float n1 = fmaxf(a1, b1v);
            float n2 = fminf(a1, b1v);
            n2 = fmaxf(n2, fmaxf(a2, b2v) == fmaxf(fmaxf(a2, b2v), n2) ? fmaxf(a2, b2v) : n2);
            // simpler: n2 = max(min(a1,b1v), max(a2,b2v)) is correct top-2 merge
            n2 = fmaxf(fminf(a1, b1v), fmaxf(a2, b2v));
            a1 = n1; a2 = n2;
        }
        const float thr = a2 - CAND_WIN;

        // exact recompute of candidates
        const float4* xr = (const float4*)(x + (size_t)t * Dk);
        uint32_t mask0 = __ballot_sync(0xFFFFFFFFu, l0 >= thr);
        uint32_t mask1 = __ballot_sync(0xFFFFFFFFu, l1 >= thr);
        while (mask0) {
            int e = __ffs(mask0) - 1; mask0 &= mask0 - 1;
            float ex = warp_dot4k(xr, (const float4*)(gw + (size_t)e * Dk), lid) + __ldg(gb + e);
            if (lid == e) l0 = ex;
        }
        while (mask1) {
            int b = __ffs(mask1) - 1; mask1 &= mask1 - 1;
            int e = b + 32;
            float ex = warp_dot4k(xr, (const float4*)(gw + (size_t)e * Dk), lid) + __ldg(gb + e);
            if (lid == b) l1 = ex;
        }

        // exact top-2 with indices (lower index wins ties)
        float v1, v2; int j1, j2;
        if (l0 > l1 || (l0 == l1)) { v1 = l0; j1 = lid; v2 = l1; j2 = lid + 32; }
        else                        { v1 = l1; j1 = lid + 32; v2 = l0; j2 = lid; }
#pragma unroll
        for (int o = 16; o > 0; o >>= 1) {
            float u1 = __shfl_xor_sync(0xFFFFFFFFu, v1, o);
            float u2 = __shfl_xor_sync(0xFFFFFFFFu, v2, o);
            int   k1 = __shfl_xor_sync(0xFFFFFFFFu, j1, o);
            int   k2 = __shfl_xor_sync(0xFFFFFFFFu, j2, o);
            // insert (u1,k1)
            if (u1 > v1 || (u1 == v1 && k1 < j1)) { v2 = v1; j2 = j1; v1 = u1; j1 = k1; }
            else if (u1 > v2 || (u1 == v2 && k1 < j2)) { v2 = u1; j2 = k1; }
            // insert (u2,k2)
            if (u2 > v1 || (u2 == v1 && k2 < j1)) { v2 = v1; j2 = j1; v1 = u2; j1 = k2; }
            else if (u2 > v2 || (u2 == v2 && k2 < j2)) { v2 = u2; j2 = k2; }
        }

        // write corrected logits for candidate entries (closer to exact; harmless)
        uint32_t cm0 = __ballot_sync(0xFFFFFFFFu, l0 >= thr);
        uint32_t cm1 = __ballot_sync(0xFFFFFFFFu, l1 >= thr);
        if (cm0 & (1u << lid)) out[(size_t)t * Ek + lid] = l0;
        if (cm1 & (1u << lid)) out[(size_t)t * Ek + lid + 32] = l1;

        if (lid == 0) {
            float ed = expf(v2 - v1);
            float w1 = 1.0f / (1.0f + ed);
            float w2 = ed * w1;
            out[offW + (size_t)t * TOPK + 0] = w1;
            out[offW + (size_t)t * TOPK + 1] = w2;
            out[offI + (size_t)t * TOPK + 0] = (float)j1;
            out[offI + (size_t)t * TOPK + 1] = (float)j2;
            out[offM + ((size_t)j1 * TOPK + 0) * (size_t)T + t] = 1.0f;
            out[offM + ((size_t)j2 * TOPK + 1) * (size_t)T + t] = 1.0f;
        }
    }
}

extern "C" void kernel_launch(void* const* d_in, const int* in_sizes, int n_in,
                              void* d_out, int out_size)
{
    const float* x  = (const float*)d_in[0];
    const float* gw = (const float*)d_in[1];
    const float* gb = (const float*)d_in[2];
    float* out = (float*)d_out;
    const int T = in_sizes[0] / Dk;

    cudaFuncSetAttribute(moe_router_mma, cudaFuncAttributeMaxDynamicSharedMemorySize, SMEM_TOTAL);

    w_prep_kernel<<<256, 256>>>((const float4*)gw);
    moe_router_mma<<<T / BM, 256, SMEM_TOTAL>>>(x, gb, out, T);
    refine_kernel<<<148, 256>>>(x, gw, gb, out, T);
}

// round 13
// speedup vs baseline: 3.1172x; 1.1507x over previous
#include <cuda_runtime.h>
#include <cuda_fp16.h>
#include <math.h>
#include <stdint.h>

// MoE Router: 1-term fp16 mma.sync GEMM (512 thr, 3-stage pipeline)
// + candidate-only exact fp32 refinement of marginal tokens.
// T=16384, D=4096, E=64, top-2.
// Output (float32): logits [T,E] | weights [T,2] | indices [T,2] | mask [E,2,T]

#define Dk 4096
#define Ek 64
#define TOPK 2
#define BM 128
#define KC 64
#define NCHUNK (Dk / KC)
#define NTHR 512
#define THETA    2.5e-3f
#define CAND_WIN 5.0e-3f

__device__ __half g_w1[Ek * Dk];    // fp16 gate weights, [E][Dk] k-major
__device__ int    g_flagcnt;
__device__ int    g_flags[16384];

// ---------------- smem layout: 3 stages of (X 16KB | W 8KB) ----------------
#define SM_BIAS 64
#define STG(s)  (1024 + (s) * 24576)
#define XS(s)   STG(s)
#define WS(s)   (STG(s) + 16384)
#define SM_LG   1024
#define SMEM_TOTAL (1024 + 3 * 24576)

// ---------------- helpers ----------------
__device__ __forceinline__ uint32_t smem_u32(const void* p) {
    uint32_t a;
    asm("{ .reg .u64 t; cvta.to.shared.u64 t, %1; cvt.u32.u64 %0, t; }" : "=r"(a) : "l"(p));
    return a;
}
__device__ __forceinline__ uint32_t pack2h(float hi, float lo) {
    uint32_t r;
    asm("cvt.rn.f16x2.f32 %0, %1, %2;" : "=r"(r) : "f"(hi), "f"(lo));
    return r;
}
__device__ __forceinline__ uint2 cvt4h(float4 v) {
    return make_uint2(pack2h(v.y, v.x), pack2h(v.w, v.z));
}
__device__ __forceinline__ void ldm_x4(uint32_t* r, uint32_t addr) {
    asm volatile("ldmatrix.sync.aligned.m8n8.x4.shared.b16 {%0,%1,%2,%3}, [%4];"
        : "=r"(r[0]), "=r"(r[1]), "=r"(r[2]), "=r"(r[3]) : "r"(addr));
}
__device__ __forceinline__ void mma_f16(float* c, const uint32_t* a, uint32_t b0, uint32_t b1) {
    asm volatile("mma.sync.aligned.m16n8k16.row.col.f32.f16.f16.f32 "
        "{%0,%1,%2,%3}, {%4,%5,%6,%7}, {%8,%9}, {%0,%1,%2,%3};"
        : "+f"(c[0]), "+f"(c[1]), "+f"(c[2]), "+f"(c[3])
        : "r"(a[0]), "r"(a[1]), "r"(a[2]), "r"(a[3]), "r"(b0), "r"(b1));
}

// ---------------- aux: convert w to fp16 + reset flag counter ----------------
__global__ void w_prep_kernel(const float4* __restrict__ gw4) {
    int i = blockIdx.x * blockDim.x + threadIdx.x;
    if (i == 0) g_flagcnt = 0;
    ((uint2*)g_w1)[i] = cvt4h(gw4[i]);
}

// ---------------- pass 1 ----------------
__global__ __launch_bounds__(NTHR, 1)
void moe_router_mma(const float* __restrict__ x,
                    const float* __restrict__ gb,
                    float* __restrict__ out, int T)
{
    extern __shared__ char smem[];
    const uint32_t sb = smem_u32(smem);
    const int tid = threadIdx.x;
    const int lid = tid & 31;
    const int wid = tid >> 5;
    const int t0 = blockIdx.x * BM;

    const size_t offW = (size_t)T * Ek;
    const size_t offI = offW + (size_t)T * TOPK;
    const size_t offM = offI + (size_t)T * TOPK;

    if (tid < 16) ((float4*)(smem + SM_BIAS))[tid] = ((const float4*)gb)[tid];

    // zero this CTA's slice of expert_mask: 128 (e,k) rows, cols [t0, t0+128)
    {
        float4 z4 = make_float4(0.f, 0.f, 0.f, 0.f);
        float* mbase = out + offM + t0;
#pragma unroll
        for (int i = tid; i < 128 * 32; i += NTHR) {
            int row = i >> 5, col = i & 31;
            ((float4*)(mbase + (size_t)row * T))[col] = z4;
        }
    }

    // ---- loader geometry: x rows xr+32*it (it<4), w one uint4/thread ----
    const int xr = tid >> 4;     // 0..31
    const int xj = tid & 15;
    uint32_t x_sts[4];
#pragma unroll
    for (int it = 0; it < 4; ++it) {
        int row = xr + 32 * it;
        x_sts[it] = (uint32_t)(row * 128 + ((xj * 8) ^ ((row & 7) << 4)));
    }
    const int wrow = tid >> 3;   // 0..63
    const int wseg = tid & 7;
    const uint32_t w_sts = (uint32_t)(wrow * 128 + ((wseg * 16) ^ ((wrow & 7) << 4)));

    // ---- mma geometry: 16 warps, warp tile 32(m) x 16(n) ----
    const int wm = wid & 3;
    const int wn = wid >> 2;
    const int lrow = lid & 15;
    const int lhi = (lid >> 4) << 4;
    const int rsw = (lrow & 7) << 4;
    int arow[2];
#pragma unroll
    for (int mi = 0; mi < 2; ++mi) arow[mi] = (32 * wm + 16 * mi + lrow) * 128;
    const int brow = (16 * wn + lrow) * 128;

    float acc[2][2][4];
#pragma unroll
    for (int mi = 0; mi < 2; ++mi)
#pragma unroll
        for (int nj = 0; nj < 2; ++nj)
#pragma unroll
            for (int q = 0; q < 4; ++q) acc[mi][nj][q] = 0.f;

    // ---- prologue: chunk 0 direct to stage 0; chunk 1 into regs ----
    {
        const float* xp = x + (size_t)(t0 + xr) * Dk + 4 * xj;
#pragma unroll
        for (int it = 0; it < 4; ++it)
            *(uint2*)(smem + XS(0) + x_sts[it]) = cvt4h(*(const float4*)(xp + (size_t)(32 * it) * Dk));
        const size_t eoff = (size_t)wrow * Dk + wseg * 8;
        *(uint4*)(smem + WS(0) + w_sts) = *(const uint4*)((const char*)g_w1 + eoff * 2);
    }
    float4 xv[4];
    uint4 w1v;
    {
        const float* xp = x + (size_t)(t0 + xr) * Dk + KC + 4 * xj;
#pragma unroll
        for (int it = 0; it < 4; ++it)
            xv[it] = *(const float4*)(xp + (size_t)(32 * it) * Dk);
        const size_t eoff = (size_t)wrow * Dk + KC + wseg * 8;
        w1v = *(const uint4*)((const char*)g_w1 + eoff * 2);
    }
    __syncthreads();

    // ---- main loop: STS(c+1), LDG(c+2), compute(c) ----
    int s_cur = 0, s_nxt = 1;
    for (int c = 0; c < NCHUNK; ++c) {
        if (c + 1 < NCHUNK) {
#pragma unroll
            for (int it = 0; it < 4; ++it)
                *(uint2*)(smem + XS(s_nxt) + x_sts[it]) = cvt4h(xv[it]);
            *(uint4*)(smem + WS(s_nxt) + w_sts) = w1v;
        }
        if (c + 2 < NCHUNK) {
            const int d2 = (c + 2) * KC;
            const float* xp = x + (size_t)(t0 + xr) * Dk + d2 + 4 * xj;
#pragma unroll
            for (int it = 0; it < 4; ++it)
                xv[it] = *(const float4*)(xp + (size_t)(32 * it) * Dk);
            const size_t eoff = (size_t)wrow * Dk + d2 + wseg * 8;
            w1v = *(const uint4*)((const char*)g_w1 + eoff * 2);
        }

        // compute chunk c from stage s_cur
        {
            const uint32_t x1_b = sb + XS(s_cur), w1_b = sb + WS(s_cur);
#pragma unroll
            for (int ks = 0; ks < 4; ++ks) {
                const uint32_t kb = (uint32_t)((ks * 32 + lhi) ^ rsw);
                uint32_t a1[2][4], b1[4];
#pragma unroll
                for (int mi = 0; mi < 2; ++mi) ldm_x4(a1[mi], x1_b + arow[mi] + kb);
                ldm_x4(b1, w1_b + brow + kb);
#pragma unroll
                for (int mi = 0; mi < 2; ++mi)
#pragma unroll
                    for (int nj = 0; nj < 2; ++nj)
                        mma_f16(acc[mi][nj], a1[mi], b1[nj], b1[nj + 2]);
            }
        }
        __syncthreads();
        s_cur = (s_cur == 2) ? 0 : s_cur + 1;
        s_nxt = (s_nxt == 2) ? 0 : s_nxt + 1;
    }

    // ---- epilogue: acc -> smem logits ----
    float* lg = (float*)(smem + SM_LG);
    {
        const int crow = 32 * wm + (lid >> 2);
        const int ccol = 16 * wn + (lid & 3) * 2;
#pragma unroll
        for (int mi = 0; mi < 2; ++mi)
#pragma unroll
            for (int nj = 0; nj < 2; ++nj) {
                const int r = crow + 16 * mi, cc = ccol + 8 * nj;
                *(float2*)&lg[r * Ek + cc]       = make_float2(acc[mi][nj][0], acc[mi][nj][1]);
                *(float2*)&lg[(r + 8) * Ek + cc] = make_float2(acc[mi][nj][2], acc[mi][nj][3]);
            }
    }
    __syncthreads();

    // add bias, write logits to gmem + smem
    const float* bs = (const float*)(smem + SM_BIAS);
    {
        const int tl = tid >> 2, eh = (tid & 3) * 16;
        float* lr = lg + tl * Ek + eh;
        float4* orow = (float4*)(out + (size_t)(t0 + tl) * Ek + eh);
#pragma unroll
        for (int q = 0; q < 4; ++q) {
            float4 v = *(float4*)(lr + 4 * q);
            v.x += bs[eh + 4 * q + 0];
            v.y += bs[eh + 4 * q + 1];
            v.z += bs[eh + 4 * q + 2];
            v.w += bs[eh + 4 * q + 3];
            orow[q] = v;
            *(float4*)(lr + 4 * q) = v;
        }
    }
    __syncthreads();

    // per-token: top-3 margin test -> finalize or flag
    if (tid < BM) {
        const int t = t0 + tid;
        const float* lr = lg + tid * Ek;
        float m1 = -INFINITY, m2 = -INFINITY, m3 = -INFINITY;
        int i1 = 0, i2 = 0;
#pragma unroll
        for (int e = 0; e < Ek; ++e) {
            float z = lr[e];
            if (z > m1)      { m3 = m2; m2 = m1; i2 = i1; m1 = z; i1 = e; }
            else if (z > m2) { m3 = m2; m2 = z; i2 = e; }
            else if (z > m3) { m3 = z; }
        }
        if ((m1 - m2 < THETA) || (m2 - m3 < THETA)) {
            int slot = atomicAdd(&g_flagcnt, 1);
            g_flags[slot] = t;
        } else {
            float ed = expf(m2 - m1);
            float w1 = 1.0f / (1.0f + ed);
            float w2 = ed * w1;
            out[offW + (size_t)t * TOPK + 0] = w1;
            out[offW + (size_t)t * TOPK + 1] = w2;
            out[offI + (size_t)t * TOPK + 0] = (float)i1;
            out[offI + (size_t)t * TOPK + 1] = (float)i2;
            out[offM + ((size_t)i1 * TOPK + 0) * (size_t)T + t] = 1.0f;
            out[offM + ((size_t)i2 * TOPK + 1) * (size_t)T + t] = 1.0f;
        }
    }
}

// ---------------- pass 2: candidate-only exact refinement, warp per token ----------------
__device__ __forceinline__ float warp_dot4k(const float4* __restrict__ xr,
                                            const float4* __restrict__ wr, int lid) {
    float a = 0.f;
#pragma unroll 8
    for (int i = lid; i < Dk / 4; i += 32) {
        float4 xv = xr[i], wv = wr[i];
        a = fmaf(xv.x, wv.x, a); a = fmaf(xv.y, wv.y, a);
        a = fmaf(xv.z, wv.z, a); a = fmaf(xv.w, wv.w, a);
    }
#pragma unroll
    for (int o = 16; o > 0; o >>= 1) a += __shfl_xor_sync(0xFFFFFFFFu, a, o);
    return a;
}

__global__ __launch_bounds__(256)
void refine_kernel(const float* __restrict__ x,
                   const float* __restrict__ gw,
                   const float* __restrict__ gb,
                   float* __restrict__ out, int T)
{
    const int lid = threadIdx.x & 31;
    const int gwarp = (blockIdx.x * blockDim.x + threadIdx.x) >> 5;
    const int nwarps = (gridDim.x * blockDim.x) >> 5;
    const int nflag = g_flagcnt;

    const size_t offW = (size_t)T * Ek;
    const size_t offI = offW + (size_t)T * TOPK;
    const size_t offM = offI + (size_t)T * TOPK;

    for (int fi = gwarp; fi < nflag; fi += nwarps) {
        const int t = g_flags[fi];
        const float* lrow = out + (size_t)t * Ek;
        float l0 = lrow[lid];         // experts lid, lid+32
        float l1 = lrow[lid + 32];

        // approx top-2 values across warp -> candidate window
        float a1 = fmaxf(l0, l1), a2 = fminf(l0, l1);
#pragma unroll
        for (int o = 16; o > 0; o >>= 1) {
            float b1v = __shfl_xor_sync(0xFFFFFFFFu, a1, o);
            float b2v = __shfl_xor_sync(0xFFFFFFFFu, a2, o);
            float n1 = fmaxf(a1, b1v);
            float n2 = fmaxf(fminf(a1, b1v), fmaxf(a2, b2v));
            a1 = n1; a2 = n2;
        }
        const float thr = a2 - CAND_WIN;

        // exact recompute of candidates
        const float4* xr = (const float4*)(x + (size_t)t * Dk);
        uint32_t mask0 = __ballot_sync(0xFFFFFFFFu, l0 >= thr);
        uint32_t mask1 = __ballot_sync(0xFFFFFFFFu, l1 >= thr);
        while (mask0) {
            int e = __ffs(mask0) - 1; mask0 &= mask0 - 1;
            float ex = warp_dot4k(xr, (const float4*)(gw + (size_t)e * Dk), lid) + __ldg(gb + e);
            if (lid == e) l0 = ex;
        }
        while (mask1) {
            int b = __ffs(mask1) - 1; mask1 &= mask1 - 1;
            int e = b + 32;
            float ex = warp_dot4k(xr, (const float4*)(gw + (size_t)e * Dk), lid) + __ldg(gb + e);
            if (lid == b) l1 = ex;
        }

        // exact top-2 with indices (lower index wins ties)
        float v1, v2; int j1, j2;
        if (l0 >= l1) { v1 = l0; j1 = lid; v2 = l1; j2 = lid + 32; }
        else          { v1 = l1; j1 = lid + 32; v2 = l0; j2 = lid; }
#pragma unroll
        for (int o = 16; o > 0; o >>= 1) {
            float u1 = __shfl_xor_sync(0xFFFFFFFFu, v1, o);
            float u2 = __shfl_xor_sync(0xFFFFFFFFu, v2, o);
            int   k1 = __shfl_xor_sync(0xFFFFFFFFu, j1, o);
            int   k2 = __shfl_xor_sync(0xFFFFFFFFu, j2, o);
            if (u1 > v1 || (u1 == v1 && k1 < j1)) { v2 = v1; j2 = j1; v1 = u1; j1 = k1; }
            else if (u1 > v2 || (u1 == v2 && k1 < j2)) { v2 = u1; j2 = k1; }
            if (u2 > v1 || (u2 == v1 && k2 < j1)) { v2 = v1; j2 = j1; v1 = u2; j1 = k2; }
            else if (u2 > v2 || (u2 == v2 && k2 < j2)) { v2 = u2; j2 = k2; }
        }

        // write corrected logits for candidate entries
        uint32_t cm0 = __ballot_sync(0xFFFFFFFFu, l0 >= thr);
        uint32_t cm1 = __ballot_sync(0xFFFFFFFFu, l1 >= thr);
        if (cm0 & (1u << lid)) out[(size_t)t * Ek + lid] = l0;
        if (cm1 & (1u << lid)) out[(size_t)t * Ek + lid + 32] = l1;

        if (lid == 0) {
            float ed = expf(v2 - v1);
            float w1 = 1.0f / (1.0f + ed);
            float w2 = ed * w1;
            out[offW + (size_t)t * TOPK + 0] = w1;
            out[offW + (size_t)t * TOPK + 1] = w2;
            out[offI + (size_t)t * TOPK + 0] = (float)j1;
            out[offI + (size_t)t * TOPK + 1] = (float)j2;
            out[offM + ((size_t)j1 * TOPK + 0) * (size_t)T + t] = 1.0f;
            out[offM + ((size_t)j2 * TOPK + 1) * (size_t)T + t] = 1.0f;
        }
    }
}

extern "C" void kernel_launch(void* const* d_in, const int* in_sizes, int n_in,
                              void* d_out, int out_size)
{
    const float* x  = (const float*)d_in[0];
    const float* gw = (const float*)d_in[1];
    const float* gb = (const float*)d_in[2];
    float* out = (float*)d_out;
    const int T = in_sizes[0] / Dk;

    cudaFuncSetAttribute(moe_router_mma, cudaFuncAttributeMaxDynamicSharedMemorySize, SMEM_TOTAL);

    w_prep_kernel<<<256, 256>>>((const float4*)gw);
    moe_router_mma<<<T / BM, NTHR, SMEM_TOTAL>>>(x, gb, out, T);
    refine_kernel<<<148, 256>>>(x, gw, gb, out, T);
}